// round 11
// baseline (speedup 1.0000x reference)
#include <cuda_runtime.h>

// Batched 12-qubit state-vector simulator, sweep-fused + batch-paired f32x2.
// One CTA simulates TWO batch elements: every amplitude is a packed f32x2
// (lane0 = element 2b, lane1 = element 2b+1). All gate math uses fma.rn.f32x2
// with per-element packed coefficients -> every scalar FFMA becomes one FFMA2.
// State lives in SMEM as two u64 planes (X=re pair, Y=im pair), XOR-swizzled.

#define NQ     12
#define DIM    (1 << NQ)          // 4096
#define NPARAM (NQ * 4 * 5)       // 240
#define NTRIG  (NPARAM + NQ)      // 252
#define NT     256
#define NW     (NT / 32)

typedef unsigned long long u64;

// ---------------- packed f32x2 primitives ----------------
__device__ __forceinline__ u64 pk2(float a, float b) {
    u64 r; asm("mov.b64 %0, {%1, %2};" : "=l"(r) : "f"(a), "f"(b)); return r;
}
__device__ __forceinline__ u64 fma2(u64 a, u64 b, u64 c) {
    u64 d; asm("fma.rn.f32x2 %0, %1, %2, %3;" : "=l"(d) : "l"(a), "l"(b), "l"(c)); return d;
}
__device__ __forceinline__ u64 mul2(u64 a, u64 b) {
    u64 d; asm("mul.rn.f32x2 %0, %1, %2;" : "=l"(d) : "l"(a), "l"(b)); return d;
}
__device__ __forceinline__ u64 add2(u64 a, u64 b) {
    u64 d; asm("add.rn.f32x2 %0, %1, %2;" : "=l"(d) : "l"(a), "l"(b)); return d;
}
#define NEG2(v) ((v) ^ 0x8000000080000000ull)

// ---------------- scalar complex helpers (matrix precompute) ----------------
struct C2 { float r, i; };
__device__ __forceinline__ C2 cmul(C2 a, C2 b) { return { a.r*b.r - a.i*b.i, a.r*b.i + a.i*b.r }; }
__device__ __forceinline__ C2 cadd(C2 a, C2 b) { return { a.r + b.r, a.i + b.i }; }
struct M2 { C2 a, b, c, d; };
__device__ __forceinline__ M2 mmul(const M2& x, const M2& y) {
    M2 r;
    r.a = cadd(cmul(x.a, y.a), cmul(x.b, y.c));
    r.b = cadd(cmul(x.a, y.b), cmul(x.b, y.d));
    r.c = cadd(cmul(x.c, y.a), cmul(x.d, y.c));
    r.d = cadd(cmul(x.c, y.b), cmul(x.d, y.d));
    return r;
}

// XOR swizzle: conflict-free (per half-warp) for every circular 4-bit group.
__device__ __forceinline__ int physof(int i) { return i ^ ((i >> 4) & 15) ^ ((i >> 8) & 15); }

// Deposit 8 bits of t into the 12-bit positions NOT in MASK.
template<int MASK>
__device__ __forceinline__ int pdep8(int t) {
    int base = 0;
#pragma unroll
    for (int p = 0; p < 12; p++) {
        if (!((MASK >> p) & 1)) { base |= (t & 1) << p; t >>= 1; }
    }
    return base;
}

// Generic packed complex 2x2 gate on local bit LB.
// Matrix layout (12 u64): ar, ai, -ai, br, bi, -bi, cr, ci, -ci, dr, di, -di.
template<int LB>
__device__ __forceinline__ void rot16p(u64 X[16], u64 Y[16], const u64* g) {
    u64 ar = g[0], ai = g[1], nai = g[2], br = g[3], bi = g[4], nbi = g[5];
    u64 cr = g[6], ci = g[7], nci = g[8], dr = g[9], di = g[10], ndi = g[11];
#pragma unroll
    for (int m = 0; m < 16; m++) {
        if (!((m >> LB) & 1)) {
            int j = m | (1 << LB);
            u64 x0 = X[m], y0 = Y[m], x1 = X[j], y1 = Y[j];
            X[m] = fma2(ar, x0, fma2(nai, y0, fma2(br, x1, mul2(nbi, y1))));
            Y[m] = fma2(ar, y0, fma2(ai,  x0, fma2(br, y1, mul2(bi,  x1))));
            X[j] = fma2(cr, x0, fma2(nci, y0, fma2(dr, x1, mul2(ndi, y1))));
            Y[j] = fma2(cr, y0, fma2(ci,  x0, fma2(dr, y1, mul2(di,  x1))));
        }
    }
}

// Packed CRX: control local bit CB, target local bit TB.
template<int CB, int TB>
__device__ __forceinline__ void crx16p(u64 X[16], u64 Y[16], u64 cc, u64 ss) {
    u64 nss = NEG2(ss);
#pragma unroll
    for (int m = 0; m < 16; m++) {
        if (((m >> CB) & 1) && !((m >> TB) & 1)) {
            int j = m | (1 << TB);
            u64 x0 = X[m], y0 = Y[m], x1 = X[j], y1 = Y[j];
            X[m] = fma2(cc, x0, mul2(ss,  y1));
            Y[m] = fma2(cc, y0, mul2(nss, x1));
            X[j] = fma2(cc, x1, mul2(ss,  y0));
            Y[j] = fma2(cc, y1, mul2(nss, x0));
        }
    }
}

// One sweep over circularly-consecutive local bits B0..B3 (chain order):
// optional rotations (RM bitmask), then CRX edges (0->1),(1->2),(2->3).
template<int B0, int B1, int B2, int B3, int RM>
__device__ __forceinline__ void sweepP(u64* sX, u64* sY, int tid, const u64* sm,
                                       int g0, int g1, int g2, int g3,
                                       u64 c0, u64 s0, u64 c1, u64 s1,
                                       u64 c2, u64 s2)
{
    constexpr int MASK = (1 << B0) | (1 << B1) | (1 << B2) | (1 << B3);
    const int pbase = physof(pdep8<MASK>(tid));
    u64 X[16], Y[16];
#pragma unroll
    for (int m = 0; m < 16; m++) {
        int place = ((m & 1) << B0) | (((m >> 1) & 1) << B1)
                  | (((m >> 2) & 1) << B2) | (((m >> 3) & 1) << B3);
        int a = pbase ^ physof(place);
        X[m] = sX[a]; Y[m] = sY[a];
    }
    if (RM & 1) rot16p<0>(X, Y, sm + g0 * 12);
    if (RM & 2) rot16p<1>(X, Y, sm + g1 * 12);
    if (RM & 4) rot16p<2>(X, Y, sm + g2 * 12);
    if (RM & 8) rot16p<3>(X, Y, sm + g3 * 12);
    crx16p<0, 1>(X, Y, c0, s0);
    crx16p<1, 2>(X, Y, c1, s1);
    crx16p<2, 3>(X, Y, c2, s2);
#pragma unroll
    for (int m = 0; m < 16; m++) {
        int place = ((m & 1) << B0) | (((m >> 1) & 1) << B1)
                  | (((m >> 2) & 1) << B2) | (((m >> 3) & 1) << B3);
        int a = pbase ^ physof(place);
        sX[a] = X[m]; sY[a] = Y[m];
    }
}

// Packed expectation contributions for 4 local bits.
template<int B0, int B1, int B2, int B3>
__device__ __forceinline__ void expect4P(const u64* sX, const u64* sY, int tid, u64* sred)
{
    constexpr int MASK = (1 << B0) | (1 << B1) | (1 << B2) | (1 << B3);
    const int pbase = physof(pdep8<MASK>(tid));
    u64 X[16], Y[16];
#pragma unroll
    for (int m = 0; m < 16; m++) {
        int place = ((m & 1) << B0) | (((m >> 1) & 1) << B1)
                  | (((m >> 2) & 1) << B2) | (((m >> 3) & 1) << B3);
        int a = pbase ^ physof(place);
        X[m] = sX[a]; Y[m] = sY[a];
    }
    const int bits[4] = { B0, B1, B2, B3 };
#pragma unroll
    for (int k = 0; k < 4; k++) {
        u64 xr = 0, xi = 0, zz = 0;   // bit pattern 0 == (0.0f, 0.0f)
#pragma unroll
        for (int m = 0; m < 16; m++) {
            if (!((m >> k) & 1)) {
                int j = m | (1 << k);
                // Re(conj(s0)*s1), Im(conj(s0)*s1), |s0|^2-|s1|^2 (both lanes)
                xr = fma2(X[m], X[j], fma2(Y[m], Y[j], xr));
                xi = fma2(X[m], Y[j], fma2(NEG2(Y[m]), X[j], xi));
                zz = fma2(X[m], X[m], fma2(Y[m], Y[m],
                     fma2(NEG2(X[j]), X[j], fma2(NEG2(Y[j]), Y[j], zz))));
            }
        }
        // Warp reduction: packed f32x2 add + 64-bit shuffle.
#pragma unroll
        for (int o = 16; o; o >>= 1) {
            xr = add2(xr, __shfl_down_sync(0xffffffffu, xr, o));
            xi = add2(xi, __shfl_down_sync(0xffffffffu, xi, o));
            zz = add2(zz, __shfl_down_sync(0xffffffffu, zz, o));
        }
        if ((tid & 31) == 0) {
            int q = 11 - bits[k];            // qubit index (bit b <-> qubit 11-b)
            int w = tid >> 5;
            sred[(q * 3 + 0) * NW + w] = xr;
            sred[(q * 3 + 1) * NW + w] = xi;
            sred[(q * 3 + 2) * NW + w] = zz;
        }
    }
}

// Dynamic SMEM layout (u64 units)
#define OFF_SX    0
#define OFF_SY    (DIM)
#define OFF_PCC   (2 * DIM)
#define OFF_PSS   (2 * DIM + 256)
#define OFF_MATS  (2 * DIM + 512)            // 48 matrices * 12 u64
#define OFF_SRED  (OFF_MATS + 48 * 12)       // 36 * NW
#define SMEM_U64  (OFF_SRED + 36 * NW)
#define SMEM_BYTES (SMEM_U64 * 8)

__global__ void __launch_bounds__(NT, 2)
qsim_kernel(const float* __restrict__ params,
            const float* __restrict__ inputs,
            float* __restrict__ out, int B)
{
    extern __shared__ u64 dyn[];
    u64* sX   = dyn + OFF_SX;
    u64* sY   = dyn + OFF_SY;
    u64* pcc  = dyn + OFF_PCC;
    u64* pss  = dyn + OFF_PSS;
    u64* mats = dyn + OFF_MATS;
    u64* sred = dyn + OFF_SRED;

    const int tid = threadIdx.x;
    const int b   = blockIdx.x;
    const int e0  = 2 * b;
    const int e1  = (2 * b + 1 < B) ? 2 * b + 1 : 2 * b;

    // half-angle trig for both elements, packed (lane0=e0, lane1=e1)
    for (int t = tid; t < NTRIG; t += NT) {
        float th0, th1;
        if (t < NPARAM) {
            th0 = params[(size_t)e0 * NPARAM + t];
            th1 = params[(size_t)e1 * NPARAM + t];
        } else {
            th0 = inputs[(size_t)e0 * NQ + (t - NPARAM)];
            th1 = inputs[(size_t)e1 * NQ + (t - NPARAM)];
        }
        float s0, c0, s1, c1;
        sincosf(0.5f * th0, &s0, &c0);
        sincosf(0.5f * th1, &s1, &c1);
        pcc[t] = pk2(c0, c1);
        pss[t] = pk2(s0, s1);
    }
    for (int i = tid; i < DIM; i += NT) { sX[i] = 0; sY[i] = 0; }
    __syncthreads();

    // Fused rotation matrices: thread -> (layer, qubit, element lane).
    if (tid < 96) {
        int e = tid & 1, idx = tid >> 1;     // idx in [0,48)
        int l = idx / 12, q = idx % 12;
        int p = l * 60 + q * 3;
        const float* fc = reinterpret_cast<const float*>(pcc);
        const float* fs = reinterpret_cast<const float*>(pss);
        float cx = fc[2*p+e],     sx = fs[2*p+e];
        float cy = fc[2*(p+1)+e], sy = fs[2*(p+1)+e];
        float cz = fc[2*(p+2)+e], sz = fs[2*(p+2)+e];
        M2 rx = { {cx, 0.f}, {0.f, -sx}, {0.f, -sx}, {cx, 0.f} };
        M2 ry = { {cy, 0.f}, {-sy, 0.f}, {sy, 0.f},  {cy, 0.f} };
        M2 rz = { {cz, -sz}, {0.f, 0.f}, {0.f, 0.f}, {cz, sz} };
        M2 mm = mmul(rz, mmul(ry, rx));
        if (l == 0) {
            float ce = fc[2*(NPARAM+q)+e], se = fs[2*(NPARAM+q)+e];
            M2 rye = { {ce, 0.f}, {-se, 0.f}, {se, 0.f}, {ce, 0.f} };
            mm = mmul(mm, rye);
        }
        float* o = reinterpret_cast<float*>(&mats[idx * 12]);
        o[0*2+e]  = mm.a.r;  o[1*2+e]  = mm.a.i;  o[2*2+e]  = -mm.a.i;
        o[3*2+e]  = mm.b.r;  o[4*2+e]  = mm.b.i;  o[5*2+e]  = -mm.b.i;
        o[6*2+e]  = mm.c.r;  o[7*2+e]  = mm.c.i;  o[8*2+e]  = -mm.c.i;
        o[9*2+e]  = mm.d.r;  o[10*2+e] = mm.d.i;  o[11*2+e] = -mm.d.i;
    }
    if (tid == 0) sX[0] = pk2(1.f, 1.f);     // physof(0) == 0
    __syncthreads();

    // Qubit q lives on bit 11-q. Forward ring CRX(q,q+1); backward CRX(q,q-1).
#pragma unroll 1
    for (int l = 0; l < 4; l++) {
        const u64* SM = mats + l * 12 * 12;
        const int pf = l * 60 + 36;
        const int pb = l * 60 + 48;

        sweepP<11,10,9,8, 0xF>(sX, sY, tid, SM, 0,1,2,3,
            pcc[pf+0],pss[pf+0], pcc[pf+1],pss[pf+1], pcc[pf+2],pss[pf+2]);
        __syncthreads();
        sweepP<8,7,6,5, 0xE>(sX, sY, tid, SM, 0,4,5,6,
            pcc[pf+3],pss[pf+3], pcc[pf+4],pss[pf+4], pcc[pf+5],pss[pf+5]);
        __syncthreads();
        sweepP<5,4,3,2, 0xE>(sX, sY, tid, SM, 0,7,8,9,
            pcc[pf+6],pss[pf+6], pcc[pf+7],pss[pf+7], pcc[pf+8],pss[pf+8]);
        __syncthreads();
        sweepP<2,1,0,11, 0x6>(sX, sY, tid, SM, 0,10,11,0,
            pcc[pf+9],pss[pf+9], pcc[pf+10],pss[pf+10], pcc[pf+11],pss[pf+11]);
        __syncthreads();
        sweepP<0,1,2,3, 0>(sX, sY, tid, SM, 0,0,0,0,
            pcc[pb+0],pss[pb+0], pcc[pb+1],pss[pb+1], pcc[pb+2],pss[pb+2]);
        __syncthreads();
        sweepP<3,4,5,6, 0>(sX, sY, tid, SM, 0,0,0,0,
            pcc[pb+3],pss[pb+3], pcc[pb+4],pss[pb+4], pcc[pb+5],pss[pb+5]);
        __syncthreads();
        sweepP<6,7,8,9, 0>(sX, sY, tid, SM, 0,0,0,0,
            pcc[pb+6],pss[pb+6], pcc[pb+7],pss[pb+7], pcc[pb+8],pss[pb+8]);
        __syncthreads();
        sweepP<9,10,11,0, 0>(sX, sY, tid, SM, 0,0,0,0,
            pcc[pb+9],pss[pb+9], pcc[pb+10],pss[pb+10], pcc[pb+11],pss[pb+11]);
        __syncthreads();
    }

    // Expectation values, 3 register passes covering all 12 bits.
    expect4P<0, 1, 2, 3>(sX, sY, tid, sred);
    expect4P<4, 5, 6, 7>(sX, sY, tid, sred);
    expect4P<8, 9, 10, 11>(sX, sY, tid, sred);
    __syncthreads();

    if (tid < 36) {
        float a0 = 0.f, a1 = 0.f;
#pragma unroll
        for (int w = 0; w < NW; w++) {
            float2 f = *reinterpret_cast<float2*>(&sred[tid * NW + w]);
            a0 += f.x; a1 += f.y;
        }
        int q = tid / 3, comp = tid - q * 3;
        float sc = (comp == 2) ? 1.f : 2.f;
        out[(size_t)e0 * 36 + comp * 12 + q] = sc * a0;
        if (2 * b + 1 < B)
            out[(size_t)(2 * b + 1) * 36 + comp * 12 + q] = sc * a1;
    }
}

extern "C" void kernel_launch(void* const* d_in, const int* in_sizes, int n_in,
                              void* d_out, int out_size)
{
    const float* params = (const float*)d_in[0];
    const float* inputs = (const float*)d_in[1];
    int sz_p = in_sizes[0], sz_i = in_sizes[1];
    if (n_in >= 2 && sz_p < sz_i) {  // robust to input ordering
        const float* t = params; params = inputs; inputs = t;
        int ts = sz_p; sz_p = sz_i; sz_i = ts;
    }
    int B = sz_p / NPARAM;  // 1024
    cudaFuncSetAttribute(qsim_kernel, cudaFuncAttributeMaxDynamicSharedMemorySize,
                         SMEM_BYTES);
    int grid = (B + 1) / 2;
    qsim_kernel<<<grid, NT, SMEM_BYTES>>>(params, inputs, (float*)d_out, B);
}

// round 13
// speedup vs baseline: 1.2051x; 1.2051x over previous
#include <cuda_runtime.h>

// Batched 12-qubit state-vector simulator, sweep-fused, rot-CRX merged.
// One CTA per batch element; state in SMEM (XOR-swizzled float2).
// Forward ring: rotation of each target qubit fused into its incoming CRX as
// a controlled general 2x2 (ctrl=0 -> R, ctrl=1 -> RX*R), precomputed.

#define NQ     12
#define DIM    (1 << NQ)          // 4096
#define NPARAM (NQ * 4 * 5)       // 240
#define NT     256
#define NW     (NT / 32)
#define LAYF   192                // floats per layer in fused-matrix table

// ---------------- complex helpers (for matrix precompute) ----------------
struct C2 { float r, i; };
__device__ __forceinline__ C2 cmul(C2 a, C2 b) { return { a.r*b.r - a.i*b.i, a.r*b.i + a.i*b.r }; }
__device__ __forceinline__ C2 cadd(C2 a, C2 b) { return { a.r + b.r, a.i + b.i }; }
struct M2 { C2 a, b, c, d; };
__device__ __forceinline__ M2 mmul(const M2& x, const M2& y) {
    M2 r;
    r.a = cadd(cmul(x.a, y.a), cmul(x.b, y.c));
    r.b = cadd(cmul(x.a, y.b), cmul(x.b, y.d));
    r.c = cadd(cmul(x.c, y.a), cmul(x.d, y.c));
    r.d = cadd(cmul(x.c, y.b), cmul(x.d, y.d));
    return r;
}

struct M2F { float ar, ai, br, bi, cr, ci, dr, di; };

__device__ __forceinline__ M2F ldmat(const float* p) {
    float4 a = *reinterpret_cast<const float4*>(p);
    float4 b = *reinterpret_cast<const float4*>(p + 4);
    return { a.x, a.y, a.z, a.w, b.x, b.y, b.z, b.w };
}

// XOR swizzle: conflict-free (per half-warp) for every circular 4-bit group.
__device__ __forceinline__ int physof(int i) { return i ^ ((i >> 4) & 15) ^ ((i >> 8) & 15); }

// Deposit 8 bits of t into the 12-bit positions NOT in MASK.
template<int MASK>
__device__ __forceinline__ int pdep8(int t) {
    int base = 0;
#pragma unroll
    for (int p = 0; p < 12; p++) {
        if (!((MASK >> p) & 1)) { base |= (t & 1) << p; t >>= 1; }
    }
    return base;
}

// Single complex butterfly on (m, j) with matrix g.
__device__ __forceinline__ void btf1(float2 v[16], int m, int j, const M2F& g) {
    float x0 = v[m].x, y0 = v[m].y, x1 = v[j].x, y1 = v[j].y;
    v[m].x = g.ar*x0 - g.ai*y0 + g.br*x1 - g.bi*y1;
    v[m].y = g.ar*y0 + g.ai*x0 + g.br*y1 + g.bi*x1;
    v[j].x = g.cr*x0 - g.ci*y0 + g.dr*x1 - g.di*y1;
    v[j].y = g.cr*y0 + g.ci*x0 + g.dr*y1 + g.di*x1;
}

// Generic complex 2x2 gate on local bit LB of the 16-amp register block.
template<int LB>
__device__ __forceinline__ void rot16(float2 v[16], M2F g) {
#pragma unroll
    for (int m = 0; m < 16; m++)
        if (!((m >> LB) & 1)) btf1(v, m, m | (1 << LB), g);
}

// Controlled general 2x2: ctrl local bit CB, target local bit TB.
// mp -> M0 (8 floats, ctrl=0), mp+8 -> M1 (ctrl=1).
template<int CB, int TB>
__device__ __forceinline__ void cgate16(float2 v[16], const float* mp) {
    M2F g = ldmat(mp);
#pragma unroll
    for (int m = 0; m < 16; m++)
        if (!((m >> TB) & 1) && !((m >> CB) & 1)) btf1(v, m, m | (1 << TB), g);
    g = ldmat(mp + 8);
#pragma unroll
    for (int m = 0; m < 16; m++)
        if (!((m >> TB) & 1) && ((m >> CB) & 1)) btf1(v, m, m | (1 << TB), g);
}

// CRX: control local bit CB, target local bit TB. c=cos(th/2), s=sin(th/2).
template<int CB, int TB>
__device__ __forceinline__ void crx16(float2 v[16], float c, float s) {
#pragma unroll
    for (int m = 0; m < 16; m++) {
        if (((m >> CB) & 1) && !((m >> TB) & 1)) {
            int j = m | (1 << TB);
            float x0 = v[m].x, y0 = v[m].y, x1 = v[j].x, y1 = v[j].y;
            v[m].x = c*x0 + s*y1;  v[m].y = c*y0 - s*x1;
            v[j].x = c*x1 + s*y0;  v[j].y = c*y1 - s*x0;
        }
    }
}

// Register-block load/store shared by all sweeps.
template<int B0, int B1, int B2, int B3>
__device__ __forceinline__ int blk_load(const float2* st, int tid, float2 v[16]) {
    constexpr int MASK = (1 << B0) | (1 << B1) | (1 << B2) | (1 << B3);
    const int pbase = physof(pdep8<MASK>(tid));
#pragma unroll
    for (int m = 0; m < 16; m++) {
        int place = ((m & 1) << B0) | (((m >> 1) & 1) << B1)
                  | (((m >> 2) & 1) << B2) | (((m >> 3) & 1) << B3);
        v[m] = st[pbase ^ physof(place)];
    }
    return pbase;
}
template<int B0, int B1, int B2, int B3>
__device__ __forceinline__ void blk_store(float2* st, int pbase, const float2 v[16]) {
#pragma unroll
    for (int m = 0; m < 16; m++) {
        int place = ((m & 1) << B0) | (((m >> 1) & 1) << B1)
                  | (((m >> 2) & 1) << B2) | (((m >> 3) & 1) << B3);
        st[pbase ^ physof(place)] = v[m];
    }
}

// Forward sweep: optional leading plain rotation on local bit 0 (ROT0),
// then NCG merged cgates on edges (0,1),(1,2)[,(2,3)]; if NCG==2, the last
// edge (2,3) is a plain CRX with coeffs (cc, cs).
template<int B0, int B1, int B2, int B3, int ROT0, int NCG>
__device__ __forceinline__ void sweepF(float2* st, int tid,
                                       const float* rot0p, const float* edgep,
                                       float cc, float cs)
{
    float2 v[16];
    int pbase = blk_load<B0, B1, B2, B3>(st, tid, v);
    if (ROT0) rot16<0>(v, ldmat(rot0p));
    cgate16<0, 1>(v, edgep);
    cgate16<1, 2>(v, edgep + 16);
    if (NCG >= 3) cgate16<2, 3>(v, edgep + 32);
    else          crx16<2, 3>(v, cc, cs);
    blk_store<B0, B1, B2, B3>(st, pbase, v);
}

// Backward sweep: 3 plain CRX edges (0->1),(1->2),(2->3).
template<int B0, int B1, int B2, int B3>
__device__ __forceinline__ void sweepB(float2* st, int tid,
                                       float c0, float s0, float c1, float s1,
                                       float c2, float s2)
{
    float2 v[16];
    int pbase = blk_load<B0, B1, B2, B3>(st, tid, v);
    crx16<0, 1>(v, c0, s0);
    crx16<1, 2>(v, c1, s1);
    crx16<2, 3>(v, c2, s2);
    blk_store<B0, B1, B2, B3>(st, pbase, v);
}

// Expectation contributions for the 4 local bits of one group.
template<int B0, int B1, int B2, int B3>
__device__ __forceinline__ void expect4(const float2* st, int tid, float* sred)
{
    float2 v[16];
    blk_load<B0, B1, B2, B3>(st, tid, v);
    const int bits[4] = { B0, B1, B2, B3 };
#pragma unroll
    for (int k = 0; k < 4; k++) {
        float xr = 0.f, xi = 0.f, zz = 0.f;
#pragma unroll
        for (int m = 0; m < 16; m++) {
            if (!((m >> k) & 1)) {
                float2 a = v[m], c = v[m | (1 << k)];
                xr += a.x * c.x + a.y * c.y;
                xi += a.x * c.y - a.y * c.x;
                zz += a.x * a.x + a.y * a.y - c.x * c.x - c.y * c.y;
            }
        }
#pragma unroll
        for (int o = 16; o; o >>= 1) {
            xr += __shfl_down_sync(0xffffffffu, xr, o);
            xi += __shfl_down_sync(0xffffffffu, xi, o);
            zz += __shfl_down_sync(0xffffffffu, zz, o);
        }
        if ((tid & 31) == 0) {
            int q = 11 - bits[k];            // qubit index (bit b <-> qubit 11-b)
            int w = tid >> 5;
            sred[(q * 3 + 0) * NW + w] = xr;
            sred[(q * 3 + 1) * NW + w] = xi;
            sred[(q * 3 + 2) * NW + w] = zz;
        }
    }
}

__global__ void __launch_bounds__(NT, 3)
qsim_kernel(const float* __restrict__ params,
            const float* __restrict__ inputs,
            float* __restrict__ out)
{
    __shared__ float2 st[DIM];
    __shared__ float pc[NPARAM + NQ], ps[NPARAM + NQ];
    __shared__ alignas(16) float smats[4 * LAYF];   // per layer: rot0(8) + 11 edges * 16
    __shared__ float sred[36 * NW];

    const int tid = threadIdx.x;
    const int b   = blockIdx.x;

    // half-angle trig for all params + embedding inputs
    for (int t = tid; t < NPARAM + NQ; t += NT) {
        float th = (t < NPARAM) ? params[(size_t)b * NPARAM + t]
                                : inputs[(size_t)b * NQ + (t - NPARAM)];
        float s, c;
        sincosf(0.5f * th, &s, &c);
        pc[t] = c; ps[t] = s;
    }
    for (int i = tid; i < DIM; i += NT) st[i] = make_float2(0.f, 0.f);
    __syncthreads();

    // Precompute matrices: one thread per (layer, chain position k).
    // k==0: plain fused rotation of qubit 0. k=1..11: edge e=k-1 gets
    // M0 = R_k (fused rot of qubit k), M1 = RX(theta_fwd[e]) * R_k.
    if (tid < 48) {
        int l = tid / 12, k = tid % 12;
        int p = l * 60 + k * 3;
        float cx = pc[p],     sx = ps[p];
        float cy = pc[p + 1], sy = ps[p + 1];
        float cz = pc[p + 2], sz = ps[p + 2];
        M2 rx = { {cx, 0.f}, {0.f, -sx}, {0.f, -sx}, {cx, 0.f} };
        M2 ry = { {cy, 0.f}, {-sy, 0.f}, {sy, 0.f},  {cy, 0.f} };
        M2 rz = { {cz, -sz}, {0.f, 0.f}, {0.f, 0.f}, {cz, sz} };
        M2 mm = mmul(rz, mmul(ry, rx));
        if (l == 0) {
            float ce = pc[NPARAM + k], se = ps[NPARAM + k];
            M2 rye = { {ce, 0.f}, {-se, 0.f}, {se, 0.f}, {ce, 0.f} };
            mm = mmul(mm, rye);
        }
        float* base = smats + l * LAYF;
        if (k == 0) {
            float* o = base;                 // rot0 slot
            o[0] = mm.a.r; o[1] = mm.a.i; o[2] = mm.b.r; o[3] = mm.b.i;
            o[4] = mm.c.r; o[5] = mm.c.i; o[6] = mm.d.r; o[7] = mm.d.i;
        } else {
            int e = k - 1;
            float* o = base + 8 + e * 16;    // M0
            o[0] = mm.a.r; o[1] = mm.a.i; o[2] = mm.b.r; o[3] = mm.b.i;
            o[4] = mm.c.r; o[5] = mm.c.i; o[6] = mm.d.r; o[7] = mm.d.i;
            int pe = l * 60 + 36 + e;        // forward-ring param (control qubit e)
            float ec = pc[pe], es = ps[pe];
            M2 rxe = { {ec, 0.f}, {0.f, -es}, {0.f, -es}, {ec, 0.f} };
            M2 m1 = mmul(rxe, mm);           // CRX's RX after the rotation
            float* o1 = o + 8;               // M1
            o1[0] = m1.a.r; o1[1] = m1.a.i; o1[2] = m1.b.r; o1[3] = m1.b.i;
            o1[4] = m1.c.r; o1[5] = m1.c.i; o1[6] = m1.d.r; o1[7] = m1.d.i;
        }
    }
    if (tid == 0) st[0] = make_float2(1.f, 0.f);   // physof(0) == 0
    __syncthreads();

    // Qubit q lives on bit 11-q. Forward ring CRX(q,q+1); backward CRX(q,q-1).
#pragma unroll 1
    for (int l = 0; l < 4; l++) {
        const float* SMF = smats + l * LAYF;
        const int pf = l * 60 + 36;
        const int pb = l * 60 + 48;    // backward-ring params, control qubit q -> pb+(11-q)

        // qubits 0-3: rot0 + merged edges 0,1,2
        sweepF<11,10,9,8, 1,3>(st, tid, SMF, SMF + 8, 0.f, 0.f);
        __syncthreads();
        // qubits 3-6: merged edges 3,4,5
        sweepF<8,7,6,5, 0,3>(st, tid, SMF, SMF + 8 + 3*16, 0.f, 0.f);
        __syncthreads();
        // qubits 6-9: merged edges 6,7,8
        sweepF<5,4,3,2, 0,3>(st, tid, SMF, SMF + 8 + 6*16, 0.f, 0.f);
        __syncthreads();
        // qubits 9,10,11,0: merged edges 9,10 + plain CRX(11,0)
        sweepF<2,1,0,11, 0,2>(st, tid, SMF, SMF + 8 + 9*16, pc[pf+11], ps[pf+11]);
        __syncthreads();
        // backward: qubits 11,10,9,8 (bits 0,1,2,3): CRX(11,10),(10,9),(9,8)
        sweepB<0,1,2,3>(st, tid,
            pc[pb+0],ps[pb+0], pc[pb+1],ps[pb+1], pc[pb+2],ps[pb+2]);
        __syncthreads();
        sweepB<3,4,5,6>(st, tid,
            pc[pb+3],ps[pb+3], pc[pb+4],ps[pb+4], pc[pb+5],ps[pb+5]);
        __syncthreads();
        sweepB<6,7,8,9>(st, tid,
            pc[pb+6],ps[pb+6], pc[pb+7],ps[pb+7], pc[pb+8],ps[pb+8]);
        __syncthreads();
        sweepB<9,10,11,0>(st, tid,
            pc[pb+9],ps[pb+9], pc[pb+10],ps[pb+10], pc[pb+11],ps[pb+11]);
        __syncthreads();
    }

    // Expectation values, 3 register passes covering all 12 bits.
    expect4<0, 1, 2, 3>(st, tid, sred);
    expect4<4, 5, 6, 7>(st, tid, sred);
    expect4<8, 9, 10, 11>(st, tid, sred);
    __syncthreads();

    if (tid < 36) {
        float a = 0.f;
#pragma unroll
        for (int w = 0; w < NW; w++) a += sred[tid * NW + w];
        int q = tid / 3, comp = tid - q * 3;
        float val = (comp == 2) ? a : 2.f * a;
        out[(size_t)b * 36 + comp * 12 + q] = val;
    }
}

extern "C" void kernel_launch(void* const* d_in, const int* in_sizes, int n_in,
                              void* d_out, int out_size)
{
    const float* params = (const float*)d_in[0];
    const float* inputs = (const float*)d_in[1];
    int sz_p = in_sizes[0], sz_i = in_sizes[1];
    if (n_in >= 2 && sz_p < sz_i) {  // robust to input ordering
        const float* t = params; params = inputs; inputs = t;
        int ts = sz_p; sz_p = sz_i; sz_i = ts;
    }
    int B = sz_p / NPARAM;  // 1024
    qsim_kernel<<<B, NT>>>(params, inputs, (float*)d_out);
}